// round 10
// baseline (speedup 1.0000x reference)
#include <cuda_runtime.h>
#include <math.h>

#define H 1024
#define W 1024
#define NB 32
#define NPIX (1024*1024)
#define SEGS 8
#define SEGH 128

// Scratch (allocation is forbidden; use device globals)
__device__ float g_x1[33554432];
__device__ float g_i2top[NB * 32 * 3 * W];   // seg-local i2 at rows 32k..32k+2
__device__ float g_colmax[NB * SEGS * W];
__device__ float g_carry [NB * SEGS * W];

// ---------------------------------------------------------------------------
// K1: fused convA(3x3)+BN+ReLU producing x1, plus segment-local bottom-up
// column cummax; emits i2 only at the 3 lowest-index rows of each 32-row band.
// ---------------------------------------------------------------------------
#define K1_COLS 128
#define K1_CH 16

__global__ __launch_bounds__(K1_COLS) void k1_convA_colscan(
    const float* __restrict__ x,
    const float* __restrict__ wa, const float* __restrict__ pba,
    const float* __restrict__ pga, const float* __restrict__ pbta,
    const float* __restrict__ pma, const float* __restrict__ pva)
{
    __shared__ float xs[K1_CH + 2][K1_COLS + 2];
    const int tid = threadIdx.x;
    const int c0  = blockIdx.x * K1_COLS;
    const int seg = blockIdx.y;
    const int b   = blockIdx.z;
    const int h0  = seg * SEGH;
    const size_t ib = (size_t)b * NPIX;

    float w[9];
#pragma unroll
    for (int i = 0; i < 9; i++) w[i] = __ldg(&wa[i]);
    const float sa = __ldg(pga) * rsqrtf(__ldg(pva) + 1e-5f);
    const float Ba = sa * (__ldg(pba) - __ldg(pma)) + __ldg(pbta);

    float m = 0.0f;
    const int col = c0 + tid;

    for (int k = 0; k < SEGH / K1_CH; k++) {
        const int hb = h0 + SEGH - K1_CH - k * K1_CH;
        __syncthreads();
#pragma unroll
        for (int r = 0; r < K1_CH + 2; r++) {
            int g = hb - 1 + r;
            float v = 0.0f;
            if ((unsigned)g < H) v = __ldg(&x[ib + (size_t)g * W + col]);
            xs[r][tid + 1] = v;
        }
        if (tid < K1_CH + 2) {
            int g = hb - 1 + tid, c = c0 - 1;
            float v = 0.0f;
            if ((unsigned)g < H && c >= 0) v = __ldg(&x[ib + (size_t)g * W + c]);
            xs[tid][0] = v;
        } else if (tid >= 32 && tid < 32 + K1_CH + 2) {
            int g = hb - 1 + (tid - 32), c = c0 + K1_COLS;
            float v = 0.0f;
            if ((unsigned)g < H && c < W) v = __ldg(&x[ib + (size_t)g * W + c]);
            xs[tid - 32][K1_COLS + 1] = v;
        }
        __syncthreads();

        float rA[3], rB[3], rC[3];
#pragma unroll
        for (int kx = 0; kx < 3; kx++) {
            rA[kx] = xs[K1_CH - 1][tid + kx];
            rB[kx] = xs[K1_CH    ][tid + kx];
            rC[kx] = xs[K1_CH + 1][tid + kx];
        }
#pragma unroll
        for (int hh = K1_CH - 1; hh >= 0; hh--) {
            float acc = 0.0f;
#pragma unroll
            for (int kx = 0; kx < 3; kx++) {
                acc = fmaf(w[0 + kx], rA[kx], acc);
                acc = fmaf(w[3 + kx], rB[kx], acc);
                acc = fmaf(w[6 + kx], rC[kx], acc);
            }
            float v = fmaxf(fmaf(sa, acc, Ba), 0.0f);
            m = fmaxf(m, v);
            const int rg = hb + hh;
            g_x1[ib + (size_t)rg * W + col] = v;
            if ((rg & 31) < 3)
                g_i2top[(((size_t)b * 32 + (rg >> 5)) * 3 + (rg & 31)) * W + col] = m;
            if (hh > 0) {
#pragma unroll
                for (int kx = 0; kx < 3; kx++) {
                    rC[kx] = rB[kx];
                    rB[kx] = rA[kx];
                    rA[kx] = xs[hh - 1][tid + kx];
                }
            }
        }
    }
    g_colmax[((size_t)b * SEGS + seg) * W + col] = m;
}

__global__ __launch_bounds__(1024) void k1b_carry()
{
    const int b   = blockIdx.x;
    const int col = threadIdx.x;
    float c = 0.0f;
#pragma unroll
    for (int s = SEGS - 1; s >= 0; s--) {
        size_t o = ((size_t)b * SEGS + s) * W + col;
        g_carry[o] = c;
        c = fmaxf(c, g_colmax[o]);
    }
}

// ---------------------------------------------------------------------------
// Packed f32x2 helpers (FFMA2 only reachable via PTX on sm_103a)
// ---------------------------------------------------------------------------
__device__ __forceinline__ unsigned long long pk2(float lo, float hi)
{
    unsigned long long r;
    asm("mov.b64 %0, {%1, %2};" : "=l"(r) : "f"(lo), "f"(hi));
    return r;
}
__device__ __forceinline__ unsigned long long fma2(
    unsigned long long a, unsigned long long b, unsigned long long c)
{
    unsigned long long d;
    asm("fma.rn.f32x2 %0, %1, %2, %3;" : "=l"(d) : "l"(a), "l"(b), "l"(c));
    return d;
}
__device__ __forceinline__ float2 upk2(unsigned long long v)
{
    float2 f;
    asm("mov.b64 {%0, %1}, %2;" : "=f"(f.x), "=f"(f.y) : "l"(v));
    return f;
}

struct Acc2 { unsigned long long xy, zw; };

// 3x3 stage on one 6-wide input row, packed math. Returns completed raw row
// (4 scalars) and shifts the two pending accumulators.
__device__ __forceinline__ void stage_apply2(
    const float r6[6], const unsigned long long wx2[9],
    Acc2& Ac, Acc2& Bc, float out4[4])
{
    unsigned long long P01 = pk2(r6[0], r6[1]);
    unsigned long long P12 = pk2(r6[1], r6[2]);
    unsigned long long P23 = pk2(r6[2], r6[3]);
    unsigned long long P34 = pk2(r6[3], r6[4]);
    unsigned long long P45 = pk2(r6[4], r6[5]);
    unsigned long long rxy = fma2(wx2[0], P01, fma2(wx2[1], P12, fma2(wx2[2], P23, Ac.xy)));
    unsigned long long rzw = fma2(wx2[0], P23, fma2(wx2[1], P34, fma2(wx2[2], P45, Ac.zw)));
    Ac.xy = fma2(wx2[3], P01, fma2(wx2[4], P12, fma2(wx2[5], P23, Bc.xy)));
    Ac.zw = fma2(wx2[3], P23, fma2(wx2[4], P34, fma2(wx2[5], P45, Bc.zw)));
    const unsigned long long z2 = 0ull;   // packed (+0.0f, +0.0f)
    Bc.xy = fma2(wx2[6], P01, fma2(wx2[7], P12, fma2(wx2[8], P23, z2)));
    Bc.zw = fma2(wx2[6], P23, fma2(wx2[7], P34, fma2(wx2[8], P45, z2)));
    float2 a = upk2(rxy), b = upk2(rzw);
    out4[0] = a.x; out4[1] = a.y; out4[2] = b.x; out4[3] = b.y;
}

// ---------------------------------------------------------------------------
// K23: bottom-up pencil, full width (256 threads x 4 cols), TWO rows per
// iteration, PROWS=64 band, local t-halos, 3 barriers per pair-iteration.
// Conv stages use packed FFMA2.
// ---------------------------------------------------------------------------
#define PROWS 64
#define WARPS 8

__device__ __forceinline__ void exchange2(
    float4 vA, float4 vB, float oA[6], float oB[6],
    float* eL, float* eR, int lane, int warp)
{
    float LA = __shfl_up_sync(0xffffffffu, vA.w, 1);
    float RA = __shfl_down_sync(0xffffffffu, vA.x, 1);
    float LB = __shfl_up_sync(0xffffffffu, vB.w, 1);
    float RB = __shfl_down_sync(0xffffffffu, vB.x, 1);
    if (lane == 31) { eL[warp] = vA.w; eL[8 + warp] = vB.w; }
    if (lane == 0)  { eR[warp] = vA.x; eR[8 + warp] = vB.x; }
    __syncthreads();
    if (lane == 0) {
        LA = warp > 0 ? eL[warp - 1] : 0.0f;
        LB = warp > 0 ? eL[8 + warp - 1] : 0.0f;
    }
    if (lane == 31) {
        RA = warp < 7 ? eR[warp + 1] : 0.0f;
        RB = warp < 7 ? eR[8 + warp + 1] : 0.0f;
    }
    oA[0] = LA; oA[1] = vA.x; oA[2] = vA.y; oA[3] = vA.z; oA[4] = vA.w; oA[5] = RA;
    oB[0] = LB; oB[1] = vB.x; oB[2] = vB.y; oB[3] = vB.z; oB[4] = vB.w; oB[5] = RB;
}

__device__ __forceinline__ float4 ldrow4(const float* p, size_t ib, int r, int col0)
{
    if ((unsigned)r < H)
        return *(const float4*)(p + ib + (size_t)r * W + col0);
    return make_float4(0.f, 0.f, 0.f, 0.f);
}

__global__ __launch_bounds__(256) void k23_pencil(
    const float* __restrict__ x,
    const float* __restrict__ wb, const float* __restrict__ pbb,
    const float* __restrict__ pgb, const float* __restrict__ pbtb,
    const float* __restrict__ pmb, const float* __restrict__ pvb,
    const float* __restrict__ pwc, const float* __restrict__ pbc,
    const float* __restrict__ pgc, const float* __restrict__ pbtc,
    const float* __restrict__ pmc, const float* __restrict__ pvc,
    const float* __restrict__ wa, const float* __restrict__ pba,
    const float* __restrict__ pga, const float* __restrict__ pbta,
    const float* __restrict__ pma, const float* __restrict__ pva,
    const float* __restrict__ wd, const float* __restrict__ pbd,
    const float* __restrict__ pwe, const float* __restrict__ pbe,
    float* __restrict__ out)
{
    __shared__ float wtA[WARPS], wtB[WARPS];
    __shared__ float eX1H[WARPS], eX1L[WARPS];
    __shared__ float eI2wH[WARPS], eI2wL[WARPS];
    __shared__ float eI2xH[WARPS], eI2xL[WARPS];
    __shared__ float eSL[16], eSR[16], eUL[16], eUR[16];

    const int tid  = threadIdx.x;
    const int lane = tid & 31;
    const int warp = tid >> 5;
    const int h0   = blockIdx.x * PROWS;
    const int b    = blockIdx.y;
    const size_t ib = (size_t)b * NPIX;
    const int col0 = tid * 4;

    const float sbn = __ldg(pgb) * rsqrtf(__ldg(pvb) + 1e-5f);
    const float Bb  = sbn * (__ldg(pbb) - __ldg(pmb)) + __ldg(pbtb);
    const float scn = __ldg(pgc) * rsqrtf(__ldg(pvc) + 1e-5f);
    const float c2x = __ldg(pwc) * scn;
    const float c2b = scn * (__ldg(pbc) - __ldg(pmc)) + __ldg(pbtc);
    const float san = __ldg(pga) * rsqrtf(__ldg(pva) + 1e-5f);
    const float Ba  = san * (__ldg(pba) - __ldg(pma)) + __ldg(pbta);
    const float bdv = __ldg(pbd);
    const float wev = __ldg(pwe);
    const float bev = __ldg(pbe);
    unsigned long long wbx2[9], wax2[9], wdx2[9];
#pragma unroll
    for (int i = 0; i < 9; i++) {
        float vb_ = __ldg(&wb[i]);
        float va_ = __ldg(&wa[i]);
        float vd_ = __ldg(&wd[i]);
        wbx2[i] = pk2(vb_, vb_);
        wax2[i] = pk2(va_, va_);
        wdx2[i] = pk2(vd_, vd_);
    }

    const float4 Z4 = make_float4(0.f, 0.f, 0.f, 0.f);
    Acc2 sAc, sBc, uAc, uBc, oAc, oBc;
    sAc.xy = sAc.zw = sBc.xy = sBc.zw = 0ull;
    uAc.xy = uAc.zw = uBc.xy = uBc.zw = 0ull;
    oAc.xy = oAc.zw = oBc.xy = oBc.zw = 0ull;
    float4 m = Z4;

    const bool warm = (h0 + PROWS) < H;
    float4 cwv = Z4;
    if (warm)
        cwv = *(const float4*)(g_carry + ((size_t)b * SEGS + ((h0 + PROWS) >> 7)) * W + col0);
    const int band = (h0 + PROWS) >> 5;

    float4 p_x1H = ldrow4(g_x1, ib, h0 + PROWS + 2, col0);
    float4 p_x1L = ldrow4(g_x1, ib, h0 + PROWS + 1, col0);
    float4 p_xH  = ldrow4(x,    ib, h0 + PROWS + 3, col0);
    float4 p_xL  = ldrow4(x,    ib, h0 + PROWS + 2, col0);

#pragma unroll 1
    for (int it = 0; it < (PROWS + 6) / 2; it++) {
        const int rH = h0 + PROWS + 2 - 2 * it;
        const int rL = rH - 1;
        float4 cx1H = p_x1H, cx1L = p_x1L, cxH = p_xH, cxL = p_xL;
        p_x1H = ldrow4(g_x1, ib, rH - 2, col0);
        p_x1L = ldrow4(g_x1, ib, rH - 3, col0);
        p_xH  = ldrow4(x,    ib, rH - 1, col0);
        p_xL  = ldrow4(x,    ib, rH - 2, col0);

        // ---- i2 per column (register; warm-up from i2top+carry) ----
        float4 i2H, i2L;
        if (it == 0) {
            i2H = Z4; i2L = Z4;
            if (warm) {
                float4 v2 = *(const float4*)(g_i2top + (((size_t)b * 32 + band) * 3 + 2) * W + col0);
                float4 v1 = *(const float4*)(g_i2top + (((size_t)b * 32 + band) * 3 + 1) * W + col0);
                i2H.x = fmaxf(v2.x, cwv.x); i2H.y = fmaxf(v2.y, cwv.y);
                i2H.z = fmaxf(v2.z, cwv.z); i2H.w = fmaxf(v2.w, cwv.w);
                i2L.x = fmaxf(v1.x, cwv.x); i2L.y = fmaxf(v1.y, cwv.y);
                i2L.z = fmaxf(v1.z, cwv.z); i2L.w = fmaxf(v1.w, cwv.w);
            }
        } else if (it == 1) {
            i2H = Z4;
            if (warm) {
                float4 v0 = *(const float4*)(g_i2top + (((size_t)b * 32 + band) * 3 + 0) * W + col0);
                i2H.x = fmaxf(v0.x, cwv.x); i2H.y = fmaxf(v0.y, cwv.y);
                i2H.z = fmaxf(v0.z, cwv.z); i2H.w = fmaxf(v0.w, cwv.w);
            }
            m = i2H;
            m.x = fmaxf(m.x, cx1L.x); m.y = fmaxf(m.y, cx1L.y);
            m.z = fmaxf(m.z, cx1L.z); m.w = fmaxf(m.w, cx1L.w);
            i2L = m;
        } else {
            m.x = fmaxf(m.x, cx1H.x); m.y = fmaxf(m.y, cx1H.y);
            m.z = fmaxf(m.z, cx1H.z); m.w = fmaxf(m.w, cx1H.w);
            i2H = m;
            m.x = fmaxf(m.x, cx1L.x); m.y = fmaxf(m.y, cx1L.y);
            m.z = fmaxf(m.z, cx1L.z); m.w = fmaxf(m.w, cx1L.w);
            i2L = m;
        }

        // ---- interleaved row suffix cummax (i1) ----
        float h3 = cx1H.w;
        float h2 = fmaxf(cx1H.z, h3);
        float h1 = fmaxf(cx1H.y, h2);
        float h0s = fmaxf(cx1H.x, h1);
        float l3 = cx1L.w;
        float l2 = fmaxf(cx1L.z, l3);
        float l1 = fmaxf(cx1L.y, l2);
        float l0s = fmaxf(cx1L.x, l1);
        float inH = h0s, inL = l0s;
#pragma unroll
        for (int off = 1; off < 32; off <<= 1) {
            inH = fmaxf(inH, __shfl_down_sync(0xffffffffu, inH, off));
            inL = fmaxf(inL, __shfl_down_sync(0xffffffffu, inL, off));
        }
        float rsH = __shfl_down_sync(0xffffffffu, inH, 1);
        float rsL = __shfl_down_sync(0xffffffffu, inL, 1);
        if (lane == 31) { rsH = 0.0f; rsL = 0.0f; }
        if (lane == 0) {
            wtA[warp] = inH; wtB[warp] = inL;
            eI2xH[warp] = i2H.x; eI2xL[warp] = i2L.x;
        }
        if (lane == 31) {
            eX1H[warp] = cx1H.w; eX1L[warp] = cx1L.w;
            eI2wH[warp] = i2H.w; eI2wL[warp] = i2L.w;
        }
        __syncthreads();                                        // bar 1
#pragma unroll
        for (int w2 = 0; w2 < WARPS; w2++)
            if (w2 > warp) { rsH = fmaxf(rsH, wtA[w2]); rsL = fmaxf(rsL, wtB[w2]); }

        // ---- t values + locally-computed halos (no barrier) ----
        float xwH = __shfl_up_sync(0xffffffffu, cx1H.w, 1);
        float iwH = __shfl_up_sync(0xffffffffu, i2H.w, 1);
        float xwL = __shfl_up_sync(0xffffffffu, cx1L.w, 1);
        float iwL = __shfl_up_sync(0xffffffffu, i2L.w, 1);
        float ixH = __shfl_down_sync(0xffffffffu, i2H.x, 1);
        float ixL = __shfl_down_sync(0xffffffffu, i2L.x, 1);
        if (lane == 0 && warp > 0) {
            xwH = eX1H[warp - 1]; iwH = eI2wH[warp - 1];
            xwL = eX1L[warp - 1]; iwL = eI2wL[warp - 1];
        }
        if (lane == 31 && warp < 7) {
            ixH = eI2xH[warp + 1]; ixL = eI2xL[warp + 1];
        }

        float sufH0 = fmaxf(h0s, rsH);
        float sufL0 = fmaxf(l0s, rsL);
        float t6H[6], t6L[6];
        t6H[1] = sufH0 + i2H.x;          t6L[1] = sufL0 + i2L.x;
        t6H[2] = fmaxf(h1, rsH) + i2H.y; t6L[2] = fmaxf(l1, rsL) + i2L.y;
        t6H[3] = fmaxf(h2, rsH) + i2H.z; t6L[3] = fmaxf(l2, rsL) + i2L.z;
        t6H[4] = fmaxf(h3, rsH) + i2H.w; t6L[4] = fmaxf(l3, rsL) + i2L.w;
        t6H[0] = fmaxf(xwH, sufH0) + iwH;
        t6L[0] = fmaxf(xwL, sufL0) + iwL;
        t6H[5] = rsH + ixH;
        t6L[5] = rsL + ixL;
        if (tid == 0)   { t6H[0] = 0.0f; t6L[0] = 0.0f; }
        if (tid == 255) { t6H[5] = 0.0f; t6L[5] = 0.0f; }
        if (rH < 0) {
#pragma unroll
            for (int j = 0; j < 6; j++) t6H[j] = 0.0f;
        }
        if (rL < 0) {
#pragma unroll
            for (int j = 0; j < 6; j++) t6L[j] = 0.0f;
        }

        // ---- s stage: completes rows rH+1, rH (packed FFMA2) ----
        float srawH[4], srawL[4];
        stage_apply2(t6H, wbx2, sAc, sBc, srawH);
        stage_apply2(t6L, wbx2, sAc, sBc, srawL);
        const int sH = rH + 1, sL = rH;
        const bool svH = ((unsigned)sH < H) && (sH >= h0 - 2) && (sH <= h0 + PROWS + 1);
        const bool svL = ((unsigned)sL < H) && (sL >= h0 - 2) && (sL <= h0 + PROWS + 1);
        float4 svalH, svalL;
        svalH.x = svH ? fmaxf(fmaf(sbn, srawH[0], Bb) + fmaf(c2x, cxH.x, c2b), 0.f) : 0.f;
        svalH.y = svH ? fmaxf(fmaf(sbn, srawH[1], Bb) + fmaf(c2x, cxH.y, c2b), 0.f) : 0.f;
        svalH.z = svH ? fmaxf(fmaf(sbn, srawH[2], Bb) + fmaf(c2x, cxH.z, c2b), 0.f) : 0.f;
        svalH.w = svH ? fmaxf(fmaf(sbn, srawH[3], Bb) + fmaf(c2x, cxH.w, c2b), 0.f) : 0.f;
        svalL.x = svL ? fmaxf(fmaf(sbn, srawL[0], Bb) + fmaf(c2x, cxL.x, c2b), 0.f) : 0.f;
        svalL.y = svL ? fmaxf(fmaf(sbn, srawL[1], Bb) + fmaf(c2x, cxL.y, c2b), 0.f) : 0.f;
        svalL.z = svL ? fmaxf(fmaf(sbn, srawL[2], Bb) + fmaf(c2x, cxL.z, c2b), 0.f) : 0.f;
        svalL.w = svL ? fmaxf(fmaf(sbn, srawL[3], Bb) + fmaf(c2x, cxL.w, c2b), 0.f) : 0.f;

        float s6H[6], s6L[6];
        exchange2(svalH, svalL, s6H, s6L, eSL, eSR, lane, warp); // bar 2

        // ---- u stage: completes rows rH+2, rH+1 ----
        float urawH[4], urawL[4];
        stage_apply2(s6H, wax2, uAc, uBc, urawH);
        stage_apply2(s6L, wax2, uAc, uBc, urawL);
        const int uH = rH + 2, uL = rH + 1;
        const bool uvH = ((unsigned)uH < H) && (uH >= h0 - 1) && (uH <= h0 + PROWS);
        const bool uvL = ((unsigned)uL < H) && (uL >= h0 - 1) && (uL <= h0 + PROWS);
        float4 uvalH, uvalL;
        uvalH.x = uvH ? fmaxf(fmaf(san, urawH[0], Ba), 0.f) : 0.f;
        uvalH.y = uvH ? fmaxf(fmaf(san, urawH[1], Ba), 0.f) : 0.f;
        uvalH.z = uvH ? fmaxf(fmaf(san, urawH[2], Ba), 0.f) : 0.f;
        uvalH.w = uvH ? fmaxf(fmaf(san, urawH[3], Ba), 0.f) : 0.f;
        uvalL.x = uvL ? fmaxf(fmaf(san, urawL[0], Ba), 0.f) : 0.f;
        uvalL.y = uvL ? fmaxf(fmaf(san, urawL[1], Ba), 0.f) : 0.f;
        uvalL.z = uvL ? fmaxf(fmaf(san, urawL[2], Ba), 0.f) : 0.f;
        uvalL.w = uvL ? fmaxf(fmaf(san, urawL[3], Ba), 0.f) : 0.f;

        float u6H[6], u6L[6];
        exchange2(uvalH, uvalL, u6H, u6L, eUL, eUR, lane, warp); // bar 3

        // ---- out stage: completes rows rH+3, rH+2 ----
        float orawH[4], orawL[4];
        stage_apply2(u6H, wdx2, oAc, oBc, orawH);
        stage_apply2(u6L, wdx2, oAc, oBc, orawL);
        const int oH = rH + 3, oL = rH + 2;
        if (oH >= h0 && oH < h0 + PROWS) {
            float4 ov;
            ov.x = fmaf(wev, fmaxf(orawH[0] + bdv, 0.f), bev);
            ov.y = fmaf(wev, fmaxf(orawH[1] + bdv, 0.f), bev);
            ov.z = fmaf(wev, fmaxf(orawH[2] + bdv, 0.f), bev);
            ov.w = fmaf(wev, fmaxf(orawH[3] + bdv, 0.f), bev);
            *(float4*)(out + ib + (size_t)oH * W + col0) = ov;
        }
        if (oL >= h0 && oL < h0 + PROWS) {
            float4 ov;
            ov.x = fmaf(wev, fmaxf(orawL[0] + bdv, 0.f), bev);
            ov.y = fmaf(wev, fmaxf(orawL[1] + bdv, 0.f), bev);
            ov.z = fmaf(wev, fmaxf(orawL[2] + bdv, 0.f), bev);
            ov.w = fmaf(wev, fmaxf(orawL[3] + bdv, 0.f), bev);
            *(float4*)(out + ib + (size_t)oL * W + col0) = ov;
        }
    }
}

// ---------------------------------------------------------------------------
extern "C" void kernel_launch(void* const* d_in, const int* in_sizes, int n_in,
                              void* d_out, int out_size)
{
    const float* x   = (const float*)d_in[0];
    const float* wa  = (const float*)d_in[1];
    const float* ba  = (const float*)d_in[2];
    const float* ga  = (const float*)d_in[3];
    const float* bta = (const float*)d_in[4];
    const float* ma  = (const float*)d_in[5];
    const float* va  = (const float*)d_in[6];
    const float* wb  = (const float*)d_in[7];
    const float* bb  = (const float*)d_in[8];
    const float* gb  = (const float*)d_in[9];
    const float* btb = (const float*)d_in[10];
    const float* mb  = (const float*)d_in[11];
    const float* vb  = (const float*)d_in[12];
    const float* wc  = (const float*)d_in[13];
    const float* bc  = (const float*)d_in[14];
    const float* gc  = (const float*)d_in[15];
    const float* btc = (const float*)d_in[16];
    const float* mc  = (const float*)d_in[17];
    const float* vc  = (const float*)d_in[18];
    const float* wd  = (const float*)d_in[19];
    const float* bd  = (const float*)d_in[20];
    const float* we  = (const float*)d_in[21];
    const float* be  = (const float*)d_in[22];
    float* out = (float*)d_out;

    dim3 g1(W / K1_COLS, SEGS, NB);
    k1_convA_colscan<<<g1, K1_COLS>>>(x, wa, ba, ga, bta, ma, va);

    k1b_carry<<<NB, 1024>>>();

    dim3 g23(H / PROWS, NB);
    k23_pencil<<<g23, 256>>>(
        x,
        wb, bb, gb, btb, mb, vb,
        wc, bc, gc, btc, mc, vc,
        wa, ba, ga, bta, ma, va,
        wd, bd, we, be,
        out);
}